// round 11
// baseline (speedup 1.0000x reference)
#include <cuda_runtime.h>
#include <cstdint>

#define N_ATOMS   131072
#define N_EDGES   1048576
#define DSTATE    64
#define N_MOLS    4096
#define ETILE     128
#define N_ETILES  (N_EDGES / ETILE)   // 8192
#define N_ATILES  (N_ATOMS / 128)     // 1024

__device__ float4 g_new_states4[N_ATOMS * DSTATE / 4];
__device__ float4 g_P4[N_ATOMS * DSTATE / 4];
__device__ float4 g_Q4[N_ATOMS * DSTATE / 4];

// counting-sort scratch
__device__ int g_cnt[N_ATOMS];
__device__ int g_c2[N_ATOMS];
__device__ int g_off[N_ATOMS];
__device__ int g_totals[128];
__device__ int g_chunkoff[128];
__device__ int g_sorted_src[N_EDGES];
__device__ int g_sorted_dst[N_EDGES];

__device__ __forceinline__ uint32_t smem_u32(const void* p) {
    uint32_t a;
    asm("{ .reg .u64 t; cvta.to.shared.u64 t, %1; cvt.u32.u64 %0, t; }" : "=r"(a) : "l"(p));
    return a;
}
__device__ __forceinline__ unsigned rna_u(float x) {
    unsigned u; asm("cvt.rna.tf32.f32 %0, %1;" : "=r"(u) : "f"(x)); return u;
}
__device__ __forceinline__ float rna_f(float x) { return __uint_as_float(rna_u(x)); }

__device__ __forceinline__ void mma8(float* c, const unsigned* a, const unsigned* b) {
    asm volatile(
        "mma.sync.aligned.m16n8k8.row.col.f32.tf32.tf32.f32 "
        "{%0,%1,%2,%3}, {%4,%5,%6,%7}, {%8,%9}, {%0,%1,%2,%3};"
        : "+f"(c[0]), "+f"(c[1]), "+f"(c[2]), "+f"(c[3])
        : "r"(a[0]), "r"(a[1]), "r"(a[2]), "r"(a[3]), "r"(b[0]), "r"(b[1]));
}

__device__ __forceinline__ void cp16(uint32_t dst, const void* src) {
    asm volatile("cp.async.cg.shared.global [%0], [%1], 16;" :: "r"(dst), "l"(src));
}
__device__ __forceinline__ void cp_commit() { asm volatile("cp.async.commit_group;" ::: "memory"); }
__device__ __forceinline__ void cp_wait0()  { asm volatile("cp.async.wait_group 0;" ::: "memory"); }
__device__ __forceinline__ void cp_wait1()  { asm volatile("cp.async.wait_group 1;" ::: "memory"); }

// ====================== counting sort by dst ======================
__global__ void __launch_bounds__(256, 4) zcnt_kernel() {
    const int i = blockIdx.x * 256 + threadIdx.x;
    ((int4*)g_cnt)[i] = make_int4(0, 0, 0, 0);
    ((int4*)g_c2)[i]  = make_int4(0, 0, 0, 0);
}

__global__ void __launch_bounds__(256, 4) count_kernel(const int* __restrict__ edge_dst) {
    const int i = blockIdx.x * 256 + threadIdx.x;
    const int4 d = ((const int4*)edge_dst)[i];
    atomicAdd(&g_cnt[d.x], 1);
    atomicAdd(&g_cnt[d.y], 1);
    atomicAdd(&g_cnt[d.z], 1);
    atomicAdd(&g_cnt[d.w], 1);
}

__global__ void __launch_bounds__(256, 4) scanA_kernel() {
    __shared__ int wsum[8], woff[8];
    const int b = blockIdx.x, tid = threadIdx.x;
    const int lane = tid & 31, w = tid >> 5;
    const int4 v = ((const int4*)g_cnt)[b * 256 + tid];
    const int t4 = v.x + v.y + v.z + v.w;
    int incl = t4;
#pragma unroll
    for (int d = 1; d < 32; d <<= 1) {
        int n = __shfl_up_sync(0xffffffffu, incl, d);
        if (lane >= d) incl += n;
    }
    if (lane == 31) wsum[w] = incl;
    __syncthreads();
    if (tid == 0) {
        int acc = 0;
#pragma unroll
        for (int i = 0; i < 8; i++) { woff[i] = acc; acc += wsum[i]; }
        g_totals[b] = acc;
    }
    __syncthreads();
    const int ex = woff[w] + incl - t4;
    int4 o;
    o.x = ex; o.y = ex + v.x; o.z = o.y + v.y; o.w = o.z + v.z;
    ((int4*)g_off)[b * 256 + tid] = o;
}

__global__ void scanB_kernel() {          // 1 block, 128 threads
    __shared__ int s[128];
    const int tid = threadIdx.x;
    const int v = g_totals[tid];
    s[tid] = v;
    __syncthreads();
    for (int d = 1; d < 128; d <<= 1) {
        int n = (tid >= d) ? s[tid - d] : 0;
        __syncthreads();
        s[tid] += n;
        __syncthreads();
    }
    g_chunkoff[tid] = s[tid] - v;         // exclusive
}

__global__ void __launch_bounds__(256, 4) scanC_kernel() {
    const int b = blockIdx.x, tid = threadIdx.x;
    const int c = g_chunkoff[b];
    int4 o = ((int4*)g_off)[b * 256 + tid];
    o.x += c; o.y += c; o.z += c; o.w += c;
    ((int4*)g_off)[b * 256 + tid] = o;
}

__global__ void __launch_bounds__(256, 4) fill_kernel(
    const int* __restrict__ edge_src, const int* __restrict__ edge_dst)
{
    const int i = blockIdx.x * 256 + threadIdx.x;
    const int4 d = ((const int4*)edge_dst)[i];
    const int4 s = ((const int4*)edge_src)[i];
    int p;
    p = g_off[d.x] + atomicAdd(&g_c2[d.x], 1); g_sorted_src[p] = s.x; g_sorted_dst[p] = d.x;
    p = g_off[d.y] + atomicAdd(&g_c2[d.y], 1); g_sorted_src[p] = s.y; g_sorted_dst[p] = d.y;
    p = g_off[d.z] + atomicAdd(&g_c2[d.z], 1); g_sorted_src[p] = s.z; g_sorted_dst[p] = d.z;
    p = g_off[d.w] + atomicAdd(&g_c2[d.w], 1); g_sorted_src[p] = s.w; g_sorted_dst[p] = d.w;
}

// ====================== P/Q precompute kernel (as R6) ======================
#define PQ_XR0  0
#define PQ_XR1  8704
#define PQ_WT   17408
#define PQ_WB   (PQ_WT + 64*68)
#define PQ_SMEM_FLOATS (PQ_WB + 64*68)
#define PQ_SMEM_BYTES  (PQ_SMEM_FLOATS * 4)

__device__ __forceinline__ void pq_layer_raw(
    const float* __restrict__ Xr, const float* __restrict__ Wt,
    float* __restrict__ gOut, int warp, int g, int t)
{
    float c[8][4];
#pragma unroll
    for (int nt = 0; nt < 8; nt++)
        c[nt][0] = c[nt][1] = c[nt][2] = c[nt][3] = 0.f;
    const unsigned* Wu = (const unsigned*)Wt;
    const int row0 = warp * 16 + g;
#pragma unroll
    for (int kt = 0; kt < 8; kt++) {
        const int kb = kt * 8;
        unsigned a[4];
        a[0] = rna_u(Xr[(row0)     * 68 + kb + t]);
        a[1] = rna_u(Xr[(row0 + 8) * 68 + kb + t]);
        a[2] = rna_u(Xr[(row0)     * 68 + kb + t + 4]);
        a[3] = rna_u(Xr[(row0 + 8) * 68 + kb + t + 4]);
#pragma unroll
        for (int nt = 0; nt < 8; nt++) {
            unsigned b[2];
            b[0] = Wu[(nt * 8 + g) * 68 + kb + t];
            b[1] = Wu[(nt * 8 + g) * 68 + kb + t + 4];
            mma8(c[nt], a, b);
        }
    }
#pragma unroll
    for (int nt = 0; nt < 8; nt++) {
        const int col = nt * 8 + 2 * t;
        *(float2*)(gOut + (size_t)(row0)     * 64 + col) = make_float2(c[nt][0], c[nt][1]);
        *(float2*)(gOut + (size_t)(row0 + 8) * 64 + col) = make_float2(c[nt][2], c[nt][3]);
    }
}

__global__ void __launch_bounds__(256, 2) pq_kernel(
    const float* __restrict__ atom_states,
    const float* __restrict__ w0)
{
    extern __shared__ float sm[];
    float* Wt = sm + PQ_WT;
    float* Wb = sm + PQ_WB;
    const uint32_t base = smem_u32(sm);

    const int tid  = threadIdx.x;
    const int warp = tid >> 5, lane = tid & 31;
    const int g = lane >> 2, t = lane & 3;
    const int stride = gridDim.x;

    for (int i = tid; i < 64 * 64; i += 256) {
        int k = i >> 6, n = i & 63;
        Wt[n * 68 + k] = rna_f(w0[k * 64 + n]);
        Wb[n * 68 + k] = rna_f(w0[(k + 64) * 64 + n]);
    }

    if (blockIdx.x < N_ATILES) {
        const float* src = atom_states + (size_t)blockIdx.x * 128 * 64;
#pragma unroll
        for (int c = 0; c < 8; c++) {
            int id = c * 256 + tid;
            int row = id >> 4, off = id & 15;
            cp16(base + (uint32_t)(PQ_XR0 + row * 68 + off * 4) * 4u,
                 src + (size_t)row * 64 + off * 4);
        }
        cp_commit();
    }

    int it = 0;
    for (int tile = blockIdx.x; tile < N_ATILES; tile += stride, it++) {
        const int tn = tile + stride;
        if (tn < N_ATILES) {
            const float* src = atom_states + (size_t)tn * 128 * 64;
            const uint32_t dbuf = ((it + 1) & 1) ? PQ_XR1 : PQ_XR0;
#pragma unroll
            for (int c = 0; c < 8; c++) {
                int id = c * 256 + tid;
                int row = id >> 4, off = id & 15;
                cp16(base + (dbuf + (uint32_t)(row * 68 + off * 4)) * 4u,
                     src + (size_t)row * 64 + off * 4);
            }
            cp_commit();
            cp_wait1();
        } else {
            cp_wait0();
        }
        __syncthreads();

        const float* Xr = sm + ((it & 1) ? PQ_XR1 : PQ_XR0);
        float* gP = (float*)g_P4 + (size_t)tile * 128 * 64;
        float* gQ = (float*)g_Q4 + (size_t)tile * 128 * 64;
        pq_layer_raw(Xr, Wt, gP, warp, g, t);
        pq_layer_raw(Xr, Wb, gQ, warp, g, t);

        float4* gz = g_new_states4 + (size_t)tile * 128 * 16;
        const float4 z = make_float4(0.f, 0.f, 0.f, 0.f);
        for (int i = tid; i < 128 * 16; i += 256) gz[i] = z;
        __syncthreads();
    }
}

// ====================== edge kernel: warp-solo + sorted edges + run-aggregated scatter ======================
#define E_A0    0                     // 128*68  (warp w owns rows [16w,16w+16); reused for msg staging)
#define E_YS    (128*68)              // 128*68
#define E_W1T   (E_YS + 128*68)       // 64*68
#define E_W2T   (E_W1T + 64*68)       // 64*68
#define E_B0    (E_W2T + 64*68)
#define E_B1    (E_B0 + 64)
#define E_B2    (E_B1 + 64)
#define E_IDX   (E_B2 + 64)           // dst[128], src[128]
#define E_SMEM_FLOATS (E_IDX + 256)
#define E_SMEM_BYTES  (E_SMEM_FLOATS * 4)

__global__ void __launch_bounds__(256, 2) edge_kernel(
    const float* __restrict__ b0,
    const float* __restrict__ w1, const float* __restrict__ b1,
    const float* __restrict__ w2, const float* __restrict__ b2)
{
    extern __shared__ float sm[];
    float* A0  = sm + E_A0;
    float* Ys  = sm + E_YS;
    float* W1t = sm + E_W1T;
    float* W2t = sm + E_W2T;
    float* bs0 = sm + E_B0;
    float* bs1 = sm + E_B1;
    float* bs2 = sm + E_B2;
    int*   sdst = (int*)(sm + E_IDX);
    int*   ssrc = sdst + 128;

    const int tid  = threadIdx.x;
    const int warp = tid >> 5, lane = tid & 31;
    const int g = lane >> 2, t = lane & 3;
    const int wbase = warp * 16;         // this warp's 16 rows

    for (int i = tid; i < 64 * 64; i += 256) {
        int k = i >> 6, n = i & 63;
        W1t[n * 68 + k] = rna_f(w1[i]);
        W2t[n * 68 + k] = rna_f(w2[i]);
    }
    if (tid < 64) { bs0[tid] = b0[tid]; bs1[tid] = b1[tid]; bs2[tid] = b2[tid]; }
    __syncthreads();   // weights/biases ready (only block barrier)

    float b1r[16], b2r[16];
#pragma unroll
    for (int nt = 0; nt < 8; nt++) {
        b1r[2*nt]   = bs1[nt * 8 + 2 * t];
        b1r[2*nt+1] = bs1[nt * 8 + 2 * t + 1];
        b2r[2*nt]   = bs2[nt * 8 + 2 * t];
        b2r[2*nt+1] = bs2[nt * 8 + 2 * t + 1];
    }

    const float* gP = (const float*)g_P4;
    const float* gQ = (const float*)g_Q4;
    float* g_new = (float*)g_new_states4;

    for (int tile = blockIdx.x; tile < N_ETILES; tile += gridDim.x) {
        const int e0 = tile * ETILE + wbase;

        // ---- this warp's 16 dst + 16 src indices (dst-sorted order) ----
        if (lane < 16)      sdst[wbase + lane]        = g_sorted_dst[e0 + lane];
        else                ssrc[wbase + (lane - 16)] = g_sorted_src[e0 + lane - 16];
        __syncwarp();

        // ---- gather + stage: A0 rows = rna(relu(P[dst] + Q[src] + b0)) ----
#pragma unroll
        for (int c = 0; c < 8; c++) {
            const int i = c * 32 + lane;
            const int rl = i >> 4, q = i & 15;
            const int r = wbase + rl;
            const float4 p = *(const float4*)(gP + (size_t)sdst[r] * 64 + q * 4);
            const float4 s = *(const float4*)(gQ + (size_t)ssrc[r] * 64 + q * 4);
            float4 o;
            o.x = rna_f(fmaxf(p.x + s.x + bs0[q * 4 + 0], 0.f));
            o.y = rna_f(fmaxf(p.y + s.y + bs0[q * 4 + 1], 0.f));
            o.z = rna_f(fmaxf(p.z + s.z + bs0[q * 4 + 2], 0.f));
            o.w = rna_f(fmaxf(p.w + s.w + bs0[q * 4 + 3], 0.f));
            *(float4*)(A0 + (size_t)r * 68 + q * 4) = o;
        }
        __syncwarp();

        // ---- L1: A0 rows x W1 -> Ys rows (rounded relu), all 64 cols ----
        {
            float c[8][4];
#pragma unroll
            for (int nt = 0; nt < 8; nt++) {
                c[nt][0] = b1r[2*nt]; c[nt][1] = b1r[2*nt+1];
                c[nt][2] = b1r[2*nt]; c[nt][3] = b1r[2*nt+1];
            }
            const unsigned* Au = (const unsigned*)A0;
            const unsigned* Wu = (const unsigned*)W1t;
            const int r0 = wbase + g;
#pragma unroll
            for (int kt = 0; kt < 8; kt++) {
                const int kb = kt * 8;
                unsigned a[4];
                a[0] = Au[(r0)     * 68 + kb + t];
                a[1] = Au[(r0 + 8) * 68 + kb + t];
                a[2] = Au[(r0)     * 68 + kb + t + 4];
                a[3] = Au[(r0 + 8) * 68 + kb + t + 4];
#pragma unroll
                for (int nt = 0; nt < 8; nt++) {
                    unsigned b[2];
                    b[0] = Wu[(nt * 8 + g) * 68 + kb + t];
                    b[1] = Wu[(nt * 8 + g) * 68 + kb + t + 4];
                    mma8(c[nt], a, b);
                }
            }
#pragma unroll
            for (int nt = 0; nt < 8; nt++) {
                const int col = nt * 8 + 2 * t;
                Ys[(r0)     * 68 + col]     = rna_f(fmaxf(c[nt][0], 0.f));
                Ys[(r0)     * 68 + col + 1] = rna_f(fmaxf(c[nt][1], 0.f));
                Ys[(r0 + 8) * 68 + col]     = rna_f(fmaxf(c[nt][2], 0.f));
                Ys[(r0 + 8) * 68 + col + 1] = rna_f(fmaxf(c[nt][3], 0.f));
            }
        }
        __syncwarp();   // Ys rows ready; A0 rows dead

        // ---- L2: Ys rows -> C; relu; stage messages into A0 rows ----
        {
            float c[8][4];
#pragma unroll
            for (int nt = 0; nt < 8; nt++) {
                c[nt][0] = b2r[2*nt]; c[nt][1] = b2r[2*nt+1];
                c[nt][2] = b2r[2*nt]; c[nt][3] = b2r[2*nt+1];
            }
            const unsigned* Au = (const unsigned*)Ys;
            const unsigned* Wu = (const unsigned*)W2t;
            const int r0 = wbase + g;
#pragma unroll
            for (int kt = 0; kt < 8; kt++) {
                const int kb = kt * 8;
                unsigned a[4];
                a[0] = Au[(r0)     * 68 + kb + t];
                a[1] = Au[(r0 + 8) * 68 + kb + t];
                a[2] = Au[(r0)     * 68 + kb + t + 4];
                a[3] = Au[(r0 + 8) * 68 + kb + t + 4];
#pragma unroll
                for (int nt = 0; nt < 8; nt++) {
                    unsigned b[2];
                    b[0] = Wu[(nt * 8 + g) * 68 + kb + t];
                    b[1] = Wu[(nt * 8 + g) * 68 + kb + t + 4];
                    mma8(c[nt], a, b);
                }
            }
#pragma unroll
            for (int nt = 0; nt < 8; nt++) {
                const int col = nt * 8 + 2 * t;
                *(float2*)(A0 + (r0)     * 68 + col) =
                    make_float2(fmaxf(c[nt][0], 0.f), fmaxf(c[nt][1], 0.f));
                *(float2*)(A0 + (r0 + 8) * 68 + col) =
                    make_float2(fmaxf(c[nt][2], 0.f), fmaxf(c[nt][3], 0.f));
            }
        }
        __syncwarp();   // staged messages ready

        // ---- segmented reduce over sorted dst runs; one red.v2 per run per lane ----
        {
            float ax = 0.f, ay = 0.f;
            const int colb = 2 * lane;
#pragma unroll
            for (int row = 0; row < 16; row++) {
                const float2 v = *(const float2*)(A0 + (size_t)(wbase + row) * 68 + colb);
                ax += v.x; ay += v.y;
                const int d = sdst[wbase + row];
                const bool end = (row == 15) || (sdst[wbase + row + 1] != d);
                if (end) {
                    asm volatile("red.global.add.v2.f32 [%0], {%1,%2};"
                                 :: "l"(g_new + (size_t)d * 64 + colb), "f"(ax), "f"(ay) : "memory");
                    ax = 0.f; ay = 0.f;
                }
            }
        }
        __syncwarp();   // idx/A0/Ys rows free for next tile
    }
}

// ====================== readout kernel (persistent, as R6) ======================
template<int KDIM, int NT, int ASTRIDE, int WSTRIDE, int YSTRIDE, bool ROUND>
__device__ __forceinline__ void mlp_layer(
    const float* __restrict__ As, const float* __restrict__ Wt,
    const float* __restrict__ bias, float* __restrict__ Ys,
    int warp, int gg, int t)
{
    float c[NT][4];
#pragma unroll
    for (int nt = 0; nt < NT; nt++) {
        float v0 = bias[nt * 8 + 2 * t];
        float v1 = bias[nt * 8 + 2 * t + 1];
        c[nt][0] = v0; c[nt][1] = v1; c[nt][2] = v0; c[nt][3] = v1;
    }
    const unsigned* Au = (const unsigned*)As;
    const unsigned* Wu = (const unsigned*)Wt;
    const int row0 = warp * 16 + gg;
#pragma unroll
    for (int kt = 0; kt < KDIM / 8; kt++) {
        const int kb = kt * 8;
        unsigned a[4];
        a[0] = Au[(size_t)row0       * ASTRIDE + kb + t];
        a[1] = Au[(size_t)(row0 + 8) * ASTRIDE + kb + t];
        a[2] = Au[(size_t)row0       * ASTRIDE + kb + t + 4];
        a[3] = Au[(size_t)(row0 + 8) * ASTRIDE + kb + t + 4];
#pragma unroll
        for (int nt = 0; nt < NT; nt++) {
            unsigned b[2];
            b[0] = Wu[(nt * 8 + gg) * WSTRIDE + kb + t];
            b[1] = Wu[(nt * 8 + gg) * WSTRIDE + kb + t + 4];
            mma8(c[nt], a, b);
        }
    }
#pragma unroll
    for (int nt = 0; nt < NT; nt++) {
        const int col = nt * 8 + 2 * t;
        float v0 = fmaxf(c[nt][0], 0.f), v1 = fmaxf(c[nt][1], 0.f);
        float v2 = fmaxf(c[nt][2], 0.f), v3 = fmaxf(c[nt][3], 0.f);
        if (ROUND) { v0 = rna_f(v0); v1 = rna_f(v1); v2 = rna_f(v2); v3 = rna_f(v3); }
        Ys[(size_t)row0       * YSTRIDE + col]     = v0;
        Ys[(size_t)row0       * YSTRIDE + col + 1] = v1;
        Ys[(size_t)(row0 + 8) * YSTRIDE + col]     = v2;
        Ys[(size_t)(row0 + 8) * YSTRIDE + col + 1] = v3;
    }
}

#define R_XS    0
#define R_Y0    (R_XS + 128*68)
#define R_W1T   (R_Y0 + 128*68)
#define R_W2T   (R_W1T + 64*68)
#define R_W3T   (R_W2T + 64*68)
#define R_B1    (R_W3T + 16*68)
#define R_B2    (R_B1 + 64)
#define R_B3    (R_B2 + 64)
#define R_SMEM_FLOATS (R_B3 + 16)
#define R_SMEM_BYTES  (R_SMEM_FLOATS * 4)

__global__ void __launch_bounds__(256, 2) readout_kernel(
    const float* __restrict__ fc1w, const float* __restrict__ fc1b,
    const float* __restrict__ fc2w, const float* __restrict__ fc2b,
    const float* __restrict__ outw, const float* __restrict__ outb,
    float* __restrict__ out)
{
    extern __shared__ float sm[];
    float* Xs  = sm + R_XS;
    float* Y0  = sm + R_Y0;
    float* W1t = sm + R_W1T;
    float* W2t = sm + R_W2T;
    float* W3t = sm + R_W3T;
    float* bsa = sm + R_B1;
    float* bsb = sm + R_B2;
    float* bsc = sm + R_B3;

    const int tid  = threadIdx.x;
    const int warp = tid >> 5, lane = tid & 31;
    const int gg = lane >> 2, t = lane & 3;

    for (int i = tid; i < 64 * 64; i += 256) {
        int k = i >> 6, n = i & 63;
        W1t[n * 68 + k] = rna_f(fc1w[i]);
        W2t[n * 68 + k] = rna_f(fc2w[i]);
    }
    for (int i = tid; i < 64 * 16; i += 256) {
        int k = i >> 4, n = i & 15;
        W3t[n * 68 + k] = rna_f(outw[i]);
    }
    if (tid < 64) { bsa[tid] = fc1b[tid]; bsb[tid] = fc2b[tid]; }
    if (tid < 16) bsc[tid] = outb[tid];

    const float* g_new = (const float*)g_new_states4;

    for (int tile = blockIdx.x; tile < N_ATILES; tile += gridDim.x) {
        __syncthreads();
        for (int i = tid; i < 128 * 16; i += 256) {
            const int rr = i >> 4, q = i & 15;
            const float4 v = *(const float4*)(g_new + ((size_t)tile * 128 + rr) * 64 + q * 4);
            float4 o;
            o.x = rna_f(v.x); o.y = rna_f(v.y); o.z = rna_f(v.z); o.w = rna_f(v.w);
            *(float4*)(Xs + (size_t)rr * 68 + q * 4) = o;
        }
        __syncthreads();

        mlp_layer<64, 8, 68, 68, 68, true >(Xs, W1t, bsa, Y0, warp, gg, t);
        __syncthreads();
        mlp_layer<64, 8, 68, 68, 68, true >(Y0, W2t, bsb, Xs, warp, gg, t);
        __syncthreads();
        mlp_layer<64, 2, 68, 68, 16, false>(Xs, W3t, bsc, Y0, warp, gg, t);
        __syncthreads();

        if (tid < 64) {
            const int mol = tid >> 4, col = tid & 15;
            float s = 0.f;
#pragma unroll
            for (int rr = 0; rr < 32; rr++) s += Y0[(mol * 32 + rr) * 16 + col];
            out[((size_t)tile * 4 + mol) * 16 + col] = s;
        }
    }
}

extern "C" void kernel_launch(void* const* d_in, const int* in_sizes, int n_in,
                              void* d_out, int out_size) {
    const float* atom_states = (const float*)d_in[0];
    const int*   edge_src    = (const int*)d_in[1];
    const int*   edge_dst    = (const int*)d_in[2];
    const float* ms0w = (const float*)d_in[4];  const float* ms0b = (const float*)d_in[5];
    const float* ms1w = (const float*)d_in[6];  const float* ms1b = (const float*)d_in[7];
    const float* ms2w = (const float*)d_in[8];  const float* ms2b = (const float*)d_in[9];
    const float* fc1w = (const float*)d_in[10]; const float* fc1b = (const float*)d_in[11];
    const float* fc2w = (const float*)d_in[12]; const float* fc2b = (const float*)d_in[13];
    const float* outw = (const float*)d_in[14]; const float* outb = (const float*)d_in[15];
    float* out = (float*)d_out;

    cudaFuncSetAttribute(pq_kernel, cudaFuncAttributeMaxDynamicSharedMemorySize, PQ_SMEM_BYTES);
    cudaFuncSetAttribute(edge_kernel, cudaFuncAttributeMaxDynamicSharedMemorySize, E_SMEM_BYTES);
    cudaFuncSetAttribute(readout_kernel, cudaFuncAttributeMaxDynamicSharedMemorySize, R_SMEM_BYTES);

    int sms = 148;
    cudaDeviceGetAttribute(&sms, cudaDevAttrMultiProcessorCount, 0);

    // counting sort of edges by dst (overlaps pq on the same stream boundary)
    zcnt_kernel<<<128, 256>>>();
    count_kernel<<<1024, 256>>>(edge_dst);
    scanA_kernel<<<128, 256>>>();
    scanB_kernel<<<1, 128>>>();
    scanC_kernel<<<128, 256>>>();
    fill_kernel<<<1024, 256>>>(edge_src, edge_dst);

    pq_kernel<<<2 * sms, 256, PQ_SMEM_BYTES>>>(atom_states, ms0w);
    edge_kernel<<<2 * sms, 256, E_SMEM_BYTES>>>(ms0b, ms1w, ms1b, ms2w, ms2b);
    readout_kernel<<<2 * sms, 256, R_SMEM_BYTES>>>(fc1w, fc1b, fc2w, fc2b,
                                                   outw, outb, out);
}

// round 12
// speedup vs baseline: 1.3675x; 1.3675x over previous
#include <cuda_runtime.h>
#include <cuda_fp16.h>
#include <cstdint>

#define N_ATOMS   131072
#define N_EDGES   1048576
#define DSTATE    64
#define N_MOLS    4096
#define ETILE     128
#define N_ETILES  (N_EDGES / ETILE)   // 8192
#define N_ATILES  (N_ATOMS / 128)     // 1024

__device__ float4 g_new_states4[N_ATOMS * DSTATE / 4];
__device__ float4 g_P4[N_ATOMS * DSTATE / 4];
__device__ float4 g_Q4[N_ATOMS * DSTATE / 4];

__device__ __forceinline__ uint32_t smem_u32(const void* p) {
    uint32_t a;
    asm("{ .reg .u64 t; cvta.to.shared.u64 t, %1; cvt.u32.u64 %0, t; }" : "=r"(a) : "l"(p));
    return a;
}
__device__ __forceinline__ unsigned rna_u(float x) {
    unsigned u; asm("cvt.rna.tf32.f32 %0, %1;" : "=r"(u) : "f"(x)); return u;
}
__device__ __forceinline__ float rna_f(float x) { return __uint_as_float(rna_u(x)); }

// tf32 m16n8k8 (pq + readout)
__device__ __forceinline__ void mma8(float* c, const unsigned* a, const unsigned* b) {
    asm volatile(
        "mma.sync.aligned.m16n8k8.row.col.f32.tf32.tf32.f32 "
        "{%0,%1,%2,%3}, {%4,%5,%6,%7}, {%8,%9}, {%0,%1,%2,%3};"
        : "+f"(c[0]), "+f"(c[1]), "+f"(c[2]), "+f"(c[3])
        : "r"(a[0]), "r"(a[1]), "r"(a[2]), "r"(a[3]), "r"(b[0]), "r"(b[1]));
}

// fp16 m16n8k16, fp32 accum (edge)
__device__ __forceinline__ void mma16(float* c, unsigned a0, unsigned a1,
                                      unsigned a2, unsigned a3,
                                      unsigned b0, unsigned b1) {
    asm volatile(
        "mma.sync.aligned.m16n8k16.row.col.f32.f16.f16.f32 "
        "{%0,%1,%2,%3}, {%4,%5,%6,%7}, {%8,%9}, {%0,%1,%2,%3};"
        : "+f"(c[0]), "+f"(c[1]), "+f"(c[2]), "+f"(c[3])
        : "r"(a0), "r"(a1), "r"(a2), "r"(a3), "r"(b0), "r"(b1));
}

__device__ __forceinline__ unsigned packh2(float lo, float hi) {
    __half2 h = __floats2half2_rn(lo, hi);
    return *(unsigned*)&h;
}

__device__ __forceinline__ void cp16(uint32_t dst, const void* src) {
    asm volatile("cp.async.cg.shared.global [%0], [%1], 16;" :: "r"(dst), "l"(src));
}
__device__ __forceinline__ void cp_commit() { asm volatile("cp.async.commit_group;" ::: "memory"); }
__device__ __forceinline__ void cp_wait0()  { asm volatile("cp.async.wait_group 0;" ::: "memory"); }
__device__ __forceinline__ void cp_wait1()  { asm volatile("cp.async.wait_group 1;" ::: "memory"); }

// ====================== P/Q precompute kernel (as R10) ======================
#define PQ_XR0  0
#define PQ_XR1  8704
#define PQ_WT   17408
#define PQ_WB   (PQ_WT + 64*68)
#define PQ_SMEM_FLOATS (PQ_WB + 64*68)
#define PQ_SMEM_BYTES  (PQ_SMEM_FLOATS * 4)

__device__ __forceinline__ void pq_layer_raw(
    const float* __restrict__ Xr, const float* __restrict__ Wt,
    float* __restrict__ gOut, int warp, int g, int t)
{
    float c[8][4];
#pragma unroll
    for (int nt = 0; nt < 8; nt++)
        c[nt][0] = c[nt][1] = c[nt][2] = c[nt][3] = 0.f;
    const unsigned* Wu = (const unsigned*)Wt;
    const int row0 = warp * 16 + g;
#pragma unroll
    for (int kt = 0; kt < 8; kt++) {
        const int kb = kt * 8;
        unsigned a[4];
        a[0] = rna_u(Xr[(row0)     * 68 + kb + t]);
        a[1] = rna_u(Xr[(row0 + 8) * 68 + kb + t]);
        a[2] = rna_u(Xr[(row0)     * 68 + kb + t + 4]);
        a[3] = rna_u(Xr[(row0 + 8) * 68 + kb + t + 4]);
#pragma unroll
        for (int nt = 0; nt < 8; nt++) {
            unsigned b[2];
            b[0] = Wu[(nt * 8 + g) * 68 + kb + t];
            b[1] = Wu[(nt * 8 + g) * 68 + kb + t + 4];
            mma8(c[nt], a, b);
        }
    }
#pragma unroll
    for (int nt = 0; nt < 8; nt++) {
        const int col = nt * 8 + 2 * t;
        *(float2*)(gOut + (size_t)(row0)     * 64 + col) = make_float2(c[nt][0], c[nt][1]);
        *(float2*)(gOut + (size_t)(row0 + 8) * 64 + col) = make_float2(c[nt][2], c[nt][3]);
    }
}

__global__ void __launch_bounds__(256, 2) pq_kernel(
    const float* __restrict__ atom_states,
    const float* __restrict__ w0)
{
    extern __shared__ float sm[];
    float* Wt = sm + PQ_WT;
    float* Wb = sm + PQ_WB;
    const uint32_t base = smem_u32(sm);

    const int tid  = threadIdx.x;
    const int warp = tid >> 5, lane = tid & 31;
    const int g = lane >> 2, t = lane & 3;
    const int stride = gridDim.x;

    for (int i = tid; i < 64 * 64; i += 256) {
        int k = i >> 6, n = i & 63;
        Wt[n * 68 + k] = rna_f(w0[k * 64 + n]);
        Wb[n * 68 + k] = rna_f(w0[(k + 64) * 64 + n]);
    }

    if (blockIdx.x < N_ATILES) {
        const float* src = atom_states + (size_t)blockIdx.x * 128 * 64;
#pragma unroll
        for (int c = 0; c < 8; c++) {
            int id = c * 256 + tid;
            int row = id >> 4, off = id & 15;
            cp16(base + (uint32_t)(PQ_XR0 + row * 68 + off * 4) * 4u,
                 src + (size_t)row * 64 + off * 4);
        }
        cp_commit();
    }

    int it = 0;
    for (int tile = blockIdx.x; tile < N_ATILES; tile += stride, it++) {
        const int tn = tile + stride;
        if (tn < N_ATILES) {
            const float* src = atom_states + (size_t)tn * 128 * 64;
            const uint32_t dbuf = ((it + 1) & 1) ? PQ_XR1 : PQ_XR0;
#pragma unroll
            for (int c = 0; c < 8; c++) {
                int id = c * 256 + tid;
                int row = id >> 4, off = id & 15;
                cp16(base + (dbuf + (uint32_t)(row * 68 + off * 4)) * 4u,
                     src + (size_t)row * 64 + off * 4);
            }
            cp_commit();
            cp_wait1();
        } else {
            cp_wait0();
        }
        __syncthreads();

        const float* Xr = sm + ((it & 1) ? PQ_XR1 : PQ_XR0);
        float* gP = (float*)g_P4 + (size_t)tile * 128 * 64;
        float* gQ = (float*)g_Q4 + (size_t)tile * 128 * 64;
        pq_layer_raw(Xr, Wt, gP, warp, g, t);
        pq_layer_raw(Xr, Wb, gQ, warp, g, t);

        float4* gz = g_new_states4 + (size_t)tile * 128 * 16;
        const float4 z = make_float4(0.f, 0.f, 0.f, 0.f);
        for (int i = tid; i < 128 * 16; i += 256) gz[i] = z;
        __syncthreads();
    }
}

// ====================== edge kernel: warp-solo, fp16 m16n8k16, 3 CTAs/SM ======================
// smem (uint units), rows stride 36 uints (= 72 halfs = 144B, conflict-free)
#define EH_A0   0                    // 128*36
#define EH_YS   (128*36)             // 128*36
#define EH_W1   (EH_YS + 128*36)     // 64*36
#define EH_W2   (EH_W1 + 64*36)      // 64*36
#define EH_B0   (EH_W2 + 64*36)      // 64 floats
#define EH_B1   (EH_B0 + 64)
#define EH_B2   (EH_B1 + 64)
#define EH_DST  (EH_B2 + 64)         // 128 ints
#define EH_SRC  (EH_DST + 128)       // 128 ints
#define EH_UINTS (EH_SRC + 128)
#define EH_SMEM_BYTES (EH_UINTS * 4) // 57088 B -> 3 CTAs/SM

__global__ void __launch_bounds__(256, 3) edge_kernel(
    const int* __restrict__ edge_src,
    const int* __restrict__ edge_dst,
    const float* __restrict__ b0,
    const float* __restrict__ w1, const float* __restrict__ b1,
    const float* __restrict__ w2, const float* __restrict__ b2)
{
    extern __shared__ unsigned smu[];
    unsigned* A0u = smu + EH_A0;
    unsigned* Ysu = smu + EH_YS;
    unsigned* W1u = smu + EH_W1;
    unsigned* W2u = smu + EH_W2;
    float* bs0 = (float*)(smu + EH_B0);
    float* bs1 = (float*)(smu + EH_B1);
    float* bs2 = (float*)(smu + EH_B2);
    int* sdst = (int*)(smu + EH_DST);
    int* ssrc = (int*)(smu + EH_SRC);

    const int tid  = threadIdx.x;
    const int warp = tid >> 5, lane = tid & 31;
    const int g = lane >> 2, t = lane & 3;
    const int wbase = warp * 16;

    // weights -> fp16, [n][k] layout, stride 72 halfs
    for (int i = tid; i < 64 * 64; i += 256) {
        int k = i >> 6, n = i & 63;
        ((__half*)W1u)[n * 72 + k] = __float2half_rn(w1[i]);
        ((__half*)W2u)[n * 72 + k] = __float2half_rn(w2[i]);
    }
    if (tid < 64) { bs0[tid] = b0[tid]; bs1[tid] = b1[tid]; bs2[tid] = b2[tid]; }
    __syncthreads();   // only block barrier

    const float* gP = (const float*)g_P4;
    const float* gQ = (const float*)g_Q4;
    float* g_new = (float*)g_new_states4;

    for (int tile = blockIdx.x; tile < N_ETILES; tile += gridDim.x) {
        const int e0 = tile * ETILE + wbase;

        if (lane < 16)      sdst[wbase + lane]        = edge_dst[e0 + lane];
        else                ssrc[wbase + (lane - 16)] = edge_src[e0 + lane - 16];
        __syncwarp();

        // ---- gather + stage (fp16): A0 rows = h(relu(P[dst]+Q[src]+b0)) ----
#pragma unroll
        for (int c = 0; c < 8; c++) {
            const int i = c * 32 + lane;
            const int rl = i >> 4, q = i & 15;
            const int r = wbase + rl;
            const float4 p = *(const float4*)(gP + (size_t)sdst[r] * 64 + q * 4);
            const float4 s = *(const float4*)(gQ + (size_t)ssrc[r] * 64 + q * 4);
            const float ox = fmaxf(p.x + s.x + bs0[q * 4 + 0], 0.f);
            const float oy = fmaxf(p.y + s.y + bs0[q * 4 + 1], 0.f);
            const float oz = fmaxf(p.z + s.z + bs0[q * 4 + 2], 0.f);
            const float ow = fmaxf(p.w + s.w + bs0[q * 4 + 3], 0.f);
            uint2 u;
            u.x = packh2(ox, oy);
            u.y = packh2(oz, ow);
            *(uint2*)(A0u + r * 36 + q * 2) = u;
        }
        __syncwarp();

        const int r0 = wbase + g;

        // ---- L1 (fp16 k16): A0 -> Ys ----
        {
            float c[8][4];
#pragma unroll
            for (int nt = 0; nt < 8; nt++) {
                const float2 bb = *(const float2*)(bs1 + nt * 8 + 2 * t);
                c[nt][0] = bb.x; c[nt][1] = bb.y; c[nt][2] = bb.x; c[nt][3] = bb.y;
            }
#pragma unroll
            for (int kt = 0; kt < 4; kt++) {
                const int kb = kt * 8;
                const unsigned a0 = A0u[(r0)     * 36 + kb + t];
                const unsigned a1 = A0u[(r0 + 8) * 36 + kb + t];
                const unsigned a2 = A0u[(r0)     * 36 + kb + t + 4];
                const unsigned a3 = A0u[(r0 + 8) * 36 + kb + t + 4];
#pragma unroll
                for (int nt = 0; nt < 8; nt++) {
                    const unsigned b0r = W1u[(nt * 8 + g) * 36 + kb + t];
                    const unsigned b1r = W1u[(nt * 8 + g) * 36 + kb + t + 4];
                    mma16(c[nt], a0, a1, a2, a3, b0r, b1r);
                }
            }
#pragma unroll
            for (int nt = 0; nt < 8; nt++) {
                Ysu[(r0)     * 36 + nt * 4 + t] =
                    packh2(fmaxf(c[nt][0], 0.f), fmaxf(c[nt][1], 0.f));
                Ysu[(r0 + 8) * 36 + nt * 4 + t] =
                    packh2(fmaxf(c[nt][2], 0.f), fmaxf(c[nt][3], 0.f));
            }
        }
        __syncwarp();

        // ---- L2 (fp16 k16): Ys -> C; relu; direct red.v2 scatter ----
        {
            float c[8][4];
#pragma unroll
            for (int nt = 0; nt < 8; nt++) {
                const float2 bb = *(const float2*)(bs2 + nt * 8 + 2 * t);
                c[nt][0] = bb.x; c[nt][1] = bb.y; c[nt][2] = bb.x; c[nt][3] = bb.y;
            }
#pragma unroll
            for (int kt = 0; kt < 4; kt++) {
                const int kb = kt * 8;
                const unsigned a0 = Ysu[(r0)     * 36 + kb + t];
                const unsigned a1 = Ysu[(r0 + 8) * 36 + kb + t];
                const unsigned a2 = Ysu[(r0)     * 36 + kb + t + 4];
                const unsigned a3 = Ysu[(r0 + 8) * 36 + kb + t + 4];
#pragma unroll
                for (int nt = 0; nt < 8; nt++) {
                    const unsigned b0r = W2u[(nt * 8 + g) * 36 + kb + t];
                    const unsigned b1r = W2u[(nt * 8 + g) * 36 + kb + t + 4];
                    mma16(c[nt], a0, a1, a2, a3, b0r, b1r);
                }
            }
            const int da = sdst[r0], db = sdst[r0 + 8];
#pragma unroll
            for (int nt = 0; nt < 8; nt++) {
                const int col = nt * 8 + 2 * t;
                const float v0 = fmaxf(c[nt][0], 0.f), v1 = fmaxf(c[nt][1], 0.f);
                const float v2 = fmaxf(c[nt][2], 0.f), v3 = fmaxf(c[nt][3], 0.f);
                asm volatile("red.global.add.v2.f32 [%0], {%1,%2};"
                             :: "l"(g_new + (size_t)da * 64 + col), "f"(v0), "f"(v1) : "memory");
                asm volatile("red.global.add.v2.f32 [%0], {%1,%2};"
                             :: "l"(g_new + (size_t)db * 64 + col), "f"(v2), "f"(v3) : "memory");
            }
        }
        __syncwarp();
    }
}

// ====================== readout kernel (persistent, as R10) ======================
template<int KDIM, int NT, int ASTRIDE, int WSTRIDE, int YSTRIDE, bool ROUND>
__device__ __forceinline__ void mlp_layer(
    const float* __restrict__ As, const float* __restrict__ Wt,
    const float* __restrict__ bias, float* __restrict__ Ys,
    int warp, int gg, int t)
{
    float c[NT][4];
#pragma unroll
    for (int nt = 0; nt < NT; nt++) {
        float v0 = bias[nt * 8 + 2 * t];
        float v1 = bias[nt * 8 + 2 * t + 1];
        c[nt][0] = v0; c[nt][1] = v1; c[nt][2] = v0; c[nt][3] = v1;
    }
    const unsigned* Au = (const unsigned*)As;
    const unsigned* Wu = (const unsigned*)Wt;
    const int row0 = warp * 16 + gg;
#pragma unroll
    for (int kt = 0; kt < KDIM / 8; kt++) {
        const int kb = kt * 8;
        unsigned a[4];
        a[0] = Au[(size_t)row0       * ASTRIDE + kb + t];
        a[1] = Au[(size_t)(row0 + 8) * ASTRIDE + kb + t];
        a[2] = Au[(size_t)row0       * ASTRIDE + kb + t + 4];
        a[3] = Au[(size_t)(row0 + 8) * ASTRIDE + kb + t + 4];
#pragma unroll
        for (int nt = 0; nt < NT; nt++) {
            unsigned b[2];
            b[0] = Wu[(nt * 8 + gg) * WSTRIDE + kb + t];
            b[1] = Wu[(nt * 8 + gg) * WSTRIDE + kb + t + 4];
            mma8(c[nt], a, b);
        }
    }
#pragma unroll
    for (int nt = 0; nt < NT; nt++) {
        const int col = nt * 8 + 2 * t;
        float v0 = fmaxf(c[nt][0], 0.f), v1 = fmaxf(c[nt][1], 0.f);
        float v2 = fmaxf(c[nt][2], 0.f), v3 = fmaxf(c[nt][3], 0.f);
        if (ROUND) { v0 = rna_f(v0); v1 = rna_f(v1); v2 = rna_f(v2); v3 = rna_f(v3); }
        Ys[(size_t)row0       * YSTRIDE + col]     = v0;
        Ys[(size_t)row0       * YSTRIDE + col + 1] = v1;
        Ys[(size_t)(row0 + 8) * YSTRIDE + col]     = v2;
        Ys[(size_t)(row0 + 8) * YSTRIDE + col + 1] = v3;
    }
}

#define R_XS    0
#define R_Y0    (R_XS + 128*68)
#define R_W1T   (R_Y0 + 128*68)
#define R_W2T   (R_W1T + 64*68)
#define R_W3T   (R_W2T + 64*68)
#define R_B1    (R_W3T + 16*68)
#define R_B2    (R_B1 + 64)
#define R_B3    (R_B2 + 64)
#define R_SMEM_FLOATS (R_B3 + 16)
#define R_SMEM_BYTES  (R_SMEM_FLOATS * 4)

__global__ void __launch_bounds__(256, 2) readout_kernel(
    const float* __restrict__ fc1w, const float* __restrict__ fc1b,
    const float* __restrict__ fc2w, const float* __restrict__ fc2b,
    const float* __restrict__ outw, const float* __restrict__ outb,
    float* __restrict__ out)
{
    extern __shared__ float sm[];
    float* Xs  = sm + R_XS;
    float* Y0  = sm + R_Y0;
    float* W1t = sm + R_W1T;
    float* W2t = sm + R_W2T;
    float* W3t = sm + R_W3T;
    float* bsa = sm + R_B1;
    float* bsb = sm + R_B2;
    float* bsc = sm + R_B3;

    const int tid  = threadIdx.x;
    const int warp = tid >> 5, lane = tid & 31;
    const int gg = lane >> 2, t = lane & 3;

    for (int i = tid; i < 64 * 64; i += 256) {
        int k = i >> 6, n = i & 63;
        W1t[n * 68 + k] = rna_f(fc1w[i]);
        W2t[n * 68 + k] = rna_f(fc2w[i]);
    }
    for (int i = tid; i < 64 * 16; i += 256) {
        int k = i >> 4, n = i & 15;
        W3t[n * 68 + k] = rna_f(outw[i]);
    }
    if (tid < 64) { bsa[tid] = fc1b[tid]; bsb[tid] = fc2b[tid]; }
    if (tid < 16) bsc[tid] = outb[tid];

    const float* g_new = (const float*)g_new_states4;

    for (int tile = blockIdx.x; tile < N_ATILES; tile += gridDim.x) {
        __syncthreads();
        for (int i = tid; i < 128 * 16; i += 256) {
            const int rr = i >> 4, q = i & 15;
            const float4 v = *(const float4*)(g_new + ((size_t)tile * 128 + rr) * 64 + q * 4);
            float4 o;
            o.x = rna_f(v.x); o.y = rna_f(v.y); o.z = rna_f(v.z); o.w = rna_f(v.w);
            *(float4*)(Xs + (size_t)rr * 68 + q * 4) = o;
        }
        __syncthreads();

        mlp_layer<64, 8, 68, 68, 68, true >(Xs, W1t, bsa, Y0, warp, gg, t);
        __syncthreads();
        mlp_layer<64, 8, 68, 68, 68, true >(Y0, W2t, bsb, Xs, warp, gg, t);
        __syncthreads();
        mlp_layer<64, 2, 68, 68, 16, false>(Xs, W3t, bsc, Y0, warp, gg, t);
        __syncthreads();

        if (tid < 64) {
            const int mol = tid >> 4, col = tid & 15;
            float s = 0.f;
#pragma unroll
            for (int rr = 0; rr < 32; rr++) s += Y0[(mol * 32 + rr) * 16 + col];
            out[((size_t)tile * 4 + mol) * 16 + col] = s;
        }
    }
}

extern "C" void kernel_launch(void* const* d_in, const int* in_sizes, int n_in,
                              void* d_out, int out_size) {
    const float* atom_states = (const float*)d_in[0];
    const int*   edge_src    = (const int*)d_in[1];
    const int*   edge_dst    = (const int*)d_in[2];
    const float* ms0w = (const float*)d_in[4];  const float* ms0b = (const float*)d_in[5];
    const float* ms1w = (const float*)d_in[6];  const float* ms1b = (const float*)d_in[7];
    const float* ms2w = (const float*)d_in[8];  const float* ms2b = (const float*)d_in[9];
    const float* fc1w = (const float*)d_in[10]; const float* fc1b = (const float*)d_in[11];
    const float* fc2w = (const float*)d_in[12]; const float* fc2b = (const float*)d_in[13];
    const float* outw = (const float*)d_in[14]; const float* outb = (const float*)d_in[15];
    float* out = (float*)d_out;

    cudaFuncSetAttribute(pq_kernel, cudaFuncAttributeMaxDynamicSharedMemorySize, PQ_SMEM_BYTES);
    cudaFuncSetAttribute(edge_kernel, cudaFuncAttributeMaxDynamicSharedMemorySize, EH_SMEM_BYTES);
    cudaFuncSetAttribute(readout_kernel, cudaFuncAttributeMaxDynamicSharedMemorySize, R_SMEM_BYTES);

    int sms = 148;
    cudaDeviceGetAttribute(&sms, cudaDevAttrMultiProcessorCount, 0);

    pq_kernel<<<2 * sms, 256, PQ_SMEM_BYTES>>>(atom_states, ms0w);
    edge_kernel<<<3 * sms, 256, EH_SMEM_BYTES>>>(edge_src, edge_dst,
                                                 ms0b, ms1w, ms1b, ms2w, ms2b);
    readout_kernel<<<2 * sms, 256, R_SMEM_BYTES>>>(fc1w, fc1b, fc2w, fc2b,
                                                   outw, outb, out);
}

// round 13
// speedup vs baseline: 1.4660x; 1.0720x over previous
#include <cuda_runtime.h>
#include <cuda_fp16.h>
#include <cstdint>

#define N_ATOMS   131072
#define N_EDGES   1048576
#define DSTATE    64
#define N_MOLS    4096
#define ETILE     128
#define N_ETILES  (N_EDGES / ETILE)   // 8192
#define N_ATILES  (N_ATOMS / 128)     // 1024

__device__ float4 g_new_states4[N_ATOMS * DSTATE / 4];
__device__ uint4  g_Ph4[N_ATOMS * 8];   // P as fp16: 64 halfs = 8 uint4 per atom
__device__ uint4  g_Qh4[N_ATOMS * 8];

__device__ __forceinline__ uint32_t smem_u32(const void* p) {
    uint32_t a;
    asm("{ .reg .u64 t; cvta.to.shared.u64 t, %1; cvt.u32.u64 %0, t; }" : "=r"(a) : "l"(p));
    return a;
}
__device__ __forceinline__ unsigned rna_u(float x) {
    unsigned u; asm("cvt.rna.tf32.f32 %0, %1;" : "=r"(u) : "f"(x)); return u;
}
__device__ __forceinline__ float rna_f(float x) { return __uint_as_float(rna_u(x)); }

// tf32 m16n8k8 (readout)
__device__ __forceinline__ void mma8(float* c, const unsigned* a, const unsigned* b) {
    asm volatile(
        "mma.sync.aligned.m16n8k8.row.col.f32.tf32.tf32.f32 "
        "{%0,%1,%2,%3}, {%4,%5,%6,%7}, {%8,%9}, {%0,%1,%2,%3};"
        : "+f"(c[0]), "+f"(c[1]), "+f"(c[2]), "+f"(c[3])
        : "r"(a[0]), "r"(a[1]), "r"(a[2]), "r"(a[3]), "r"(b[0]), "r"(b[1]));
}

// fp16 m16n8k16, fp32 accum (pq + edge)
__device__ __forceinline__ void mma16(float* c, unsigned a0, unsigned a1,
                                      unsigned a2, unsigned a3,
                                      unsigned b0, unsigned b1) {
    asm volatile(
        "mma.sync.aligned.m16n8k16.row.col.f32.f16.f16.f32 "
        "{%0,%1,%2,%3}, {%4,%5,%6,%7}, {%8,%9}, {%0,%1,%2,%3};"
        : "+f"(c[0]), "+f"(c[1]), "+f"(c[2]), "+f"(c[3])
        : "r"(a0), "r"(a1), "r"(a2), "r"(a3), "r"(b0), "r"(b1));
}

__device__ __forceinline__ unsigned packh2(float lo, float hi) {
    __half2 h = __floats2half2_rn(lo, hi);
    return *(unsigned*)&h;
}

__device__ __forceinline__ void cp16(uint32_t dst, const void* src) {
    asm volatile("cp.async.cg.shared.global [%0], [%1], 16;" :: "r"(dst), "l"(src));
}
__device__ __forceinline__ void cp_commit() { asm volatile("cp.async.commit_group;" ::: "memory"); }
__device__ __forceinline__ void cp_wait0()  { asm volatile("cp.async.wait_group 0;" ::: "memory"); }
__device__ __forceinline__ void cp_wait1()  { asm volatile("cp.async.wait_group 1;" ::: "memory"); }

// ====================== P/Q precompute kernel (fp16 mma, fp16 output) ======================
// smem floats: XR0/XR1 fp32 staging (stride 68), Wt/Wb fp16 [n][k] (stride 72 halfs = 36 uints)
#define PQ_XR0  0
#define PQ_XR1  8704
#define PQ_W    17408                 // uints region: 2 x 64*36
#define PQ_SMEM_FLOATS (PQ_W + 2*64*36)
#define PQ_SMEM_BYTES  (PQ_SMEM_FLOATS * 4)

__device__ __forceinline__ void pq_layer_h16(
    const float* __restrict__ Xr, const unsigned* __restrict__ Wu,
    unsigned* __restrict__ gOut, int warp, int g, int t)
{
    float c[8][4];
#pragma unroll
    for (int nt = 0; nt < 8; nt++)
        c[nt][0] = c[nt][1] = c[nt][2] = c[nt][3] = 0.f;
    const int row0 = warp * 16 + g;
#pragma unroll
    for (int kt = 0; kt < 4; kt++) {
        const int kb = kt * 8;
        const int k0 = 2 * (kb + t), k1 = 2 * (kb + t + 4);
        const unsigned a0 = packh2(Xr[(row0)     * 68 + k0], Xr[(row0)     * 68 + k0 + 1]);
        const unsigned a1 = packh2(Xr[(row0 + 8) * 68 + k0], Xr[(row0 + 8) * 68 + k0 + 1]);
        const unsigned a2 = packh2(Xr[(row0)     * 68 + k1], Xr[(row0)     * 68 + k1 + 1]);
        const unsigned a3 = packh2(Xr[(row0 + 8) * 68 + k1], Xr[(row0 + 8) * 68 + k1 + 1]);
#pragma unroll
        for (int nt = 0; nt < 8; nt++) {
            const unsigned b0 = Wu[(nt * 8 + g) * 36 + kb + t];
            const unsigned b1 = Wu[(nt * 8 + g) * 36 + kb + t + 4];
            mma16(c[nt], a0, a1, a2, a3, b0, b1);
        }
    }
#pragma unroll
    for (int nt = 0; nt < 8; nt++) {
        gOut[(size_t)(row0)     * 32 + nt * 4 + t] = packh2(c[nt][0], c[nt][1]);
        gOut[(size_t)(row0 + 8) * 32 + nt * 4 + t] = packh2(c[nt][2], c[nt][3]);
    }
}

__global__ void __launch_bounds__(256, 2) pq_kernel(
    const float* __restrict__ atom_states,
    const float* __restrict__ w0)
{
    extern __shared__ float sm[];
    unsigned* Wt = (unsigned*)(sm + PQ_W);
    unsigned* Wb = Wt + 64 * 36;
    const uint32_t base = smem_u32(sm);

    const int tid  = threadIdx.x;
    const int warp = tid >> 5, lane = tid & 31;
    const int g = lane >> 2, t = lane & 3;
    const int stride = gridDim.x;

    for (int i = tid; i < 64 * 64; i += 256) {
        int k = i >> 6, n = i & 63;
        ((__half*)Wt)[n * 72 + k] = __float2half_rn(w0[k * 64 + n]);
        ((__half*)Wb)[n * 72 + k] = __float2half_rn(w0[(k + 64) * 64 + n]);
    }

    if (blockIdx.x < N_ATILES) {
        const float* src = atom_states + (size_t)blockIdx.x * 128 * 64;
#pragma unroll
        for (int c = 0; c < 8; c++) {
            int id = c * 256 + tid;
            int row = id >> 4, off = id & 15;
            cp16(base + (uint32_t)(PQ_XR0 + row * 68 + off * 4) * 4u,
                 src + (size_t)row * 64 + off * 4);
        }
        cp_commit();
    }

    int it = 0;
    for (int tile = blockIdx.x; tile < N_ATILES; tile += stride, it++) {
        const int tn = tile + stride;
        if (tn < N_ATILES) {
            const float* src = atom_states + (size_t)tn * 128 * 64;
            const uint32_t dbuf = ((it + 1) & 1) ? PQ_XR1 : PQ_XR0;
#pragma unroll
            for (int c = 0; c < 8; c++) {
                int id = c * 256 + tid;
                int row = id >> 4, off = id & 15;
                cp16(base + (dbuf + (uint32_t)(row * 68 + off * 4)) * 4u,
                     src + (size_t)row * 64 + off * 4);
            }
            cp_commit();
            cp_wait1();
        } else {
            cp_wait0();
        }
        __syncthreads();

        const float* Xr = sm + ((it & 1) ? PQ_XR1 : PQ_XR0);
        unsigned* gP = (unsigned*)g_Ph4 + (size_t)tile * 128 * 32;
        unsigned* gQ = (unsigned*)g_Qh4 + (size_t)tile * 128 * 32;
        pq_layer_h16(Xr, Wt, gP, warp, g, t);
        pq_layer_h16(Xr, Wb, gQ, warp, g, t);

        float4* gz = g_new_states4 + (size_t)tile * 128 * 16;
        const float4 z = make_float4(0.f, 0.f, 0.f, 0.f);
        for (int i = tid; i < 128 * 16; i += 256) gz[i] = z;
        __syncthreads();
    }
}

// ====================== edge kernel: warp-solo, fp16 datapath + fp16 P/Q gather ======================
#define EH_A0   0                    // 128*36 uints
#define EH_YS   (128*36)
#define EH_W1   (EH_YS + 128*36)     // 64*36
#define EH_W2   (EH_W1 + 64*36)
#define EH_B0   (EH_W2 + 64*36)      // 64 floats
#define EH_B1   (EH_B0 + 64)
#define EH_B2   (EH_B1 + 64)
#define EH_DST  (EH_B2 + 64)
#define EH_SRC  (EH_DST + 128)
#define EH_UINTS (EH_SRC + 128)
#define EH_SMEM_BYTES (EH_UINTS * 4)

__global__ void __launch_bounds__(256, 3) edge_kernel(
    const int* __restrict__ edge_src,
    const int* __restrict__ edge_dst,
    const float* __restrict__ b0,
    const float* __restrict__ w1, const float* __restrict__ b1,
    const float* __restrict__ w2, const float* __restrict__ b2)
{
    extern __shared__ unsigned smu[];
    unsigned* A0u = smu + EH_A0;
    unsigned* Ysu = smu + EH_YS;
    unsigned* W1u = smu + EH_W1;
    unsigned* W2u = smu + EH_W2;
    float* bs0 = (float*)(smu + EH_B0);
    float* bs1 = (float*)(smu + EH_B1);
    float* bs2 = (float*)(smu + EH_B2);
    int* sdst = (int*)(smu + EH_DST);
    int* ssrc = (int*)(smu + EH_SRC);

    const int tid  = threadIdx.x;
    const int warp = tid >> 5, lane = tid & 31;
    const int g = lane >> 2, t = lane & 3;
    const int wbase = warp * 16;

    for (int i = tid; i < 64 * 64; i += 256) {
        int k = i >> 6, n = i & 63;
        ((__half*)W1u)[n * 72 + k] = __float2half_rn(w1[i]);
        ((__half*)W2u)[n * 72 + k] = __float2half_rn(w2[i]);
    }
    if (tid < 64) { bs0[tid] = b0[tid]; bs1[tid] = b1[tid]; bs2[tid] = b2[tid]; }
    __syncthreads();

    const uint4* gP = g_Ph4;
    const uint4* gQ = g_Qh4;
    float* g_new = (float*)g_new_states4;

    for (int tile = blockIdx.x; tile < N_ETILES; tile += gridDim.x) {
        const int e0 = tile * ETILE + wbase;

        if (lane < 16)      sdst[wbase + lane]        = edge_dst[e0 + lane];
        else                ssrc[wbase + (lane - 16)] = edge_src[e0 + lane - 16];
        __syncwarp();

        // ---- gather (fp16) + stage: A0 = h(relu(P[dst]+Q[src]+b0)) ----
        // 16 rows x 8 chunks (8 halfs each) = 128 chunks; 4 per lane
#pragma unroll
        for (int c = 0; c < 4; c++) {
            const int i = c * 32 + lane;
            const int rl = i >> 3, q = i & 7;       // row-local, chunk id
            const int r = wbase + rl;
            const uint4 pu = gP[(size_t)sdst[r] * 8 + q];
            const uint4 su = gQ[(size_t)ssrc[r] * 8 + q];
            const __half2* ph = (const __half2*)&pu;
            const __half2* sh = (const __half2*)&su;
            uint4 o;
            unsigned* ou = (unsigned*)&o;
#pragma unroll
            for (int j = 0; j < 4; j++) {
                const float2 pf = __half22float2(ph[j]);
                const float2 sf = __half22float2(sh[j]);
                const int col = q * 8 + 2 * j;
                ou[j] = packh2(fmaxf(pf.x + sf.x + bs0[col],     0.f),
                               fmaxf(pf.y + sf.y + bs0[col + 1], 0.f));
            }
            *(uint4*)(A0u + (size_t)r * 36 + q * 4) = o;
        }
        __syncwarp();

        const int r0 = wbase + g;

        // ---- L1 (fp16 k16): A0 -> Ys ----
        {
            float c[8][4];
#pragma unroll
            for (int nt = 0; nt < 8; nt++) {
                const float2 bb = *(const float2*)(bs1 + nt * 8 + 2 * t);
                c[nt][0] = bb.x; c[nt][1] = bb.y; c[nt][2] = bb.x; c[nt][3] = bb.y;
            }
#pragma unroll
            for (int kt = 0; kt < 4; kt++) {
                const int kb = kt * 8;
                const unsigned a0 = A0u[(r0)     * 36 + kb + t];
                const unsigned a1 = A0u[(r0 + 8) * 36 + kb + t];
                const unsigned a2 = A0u[(r0)     * 36 + kb + t + 4];
                const unsigned a3 = A0u[(r0 + 8) * 36 + kb + t + 4];
#pragma unroll
                for (int nt = 0; nt < 8; nt++) {
                    const unsigned b0r = W1u[(nt * 8 + g) * 36 + kb + t];
                    const unsigned b1r = W1u[(nt * 8 + g) * 36 + kb + t + 4];
                    mma16(c[nt], a0, a1, a2, a3, b0r, b1r);
                }
            }
#pragma unroll
            for (int nt = 0; nt < 8; nt++) {
                Ysu[(r0)     * 36 + nt * 4 + t] =
                    packh2(fmaxf(c[nt][0], 0.f), fmaxf(c[nt][1], 0.f));
                Ysu[(r0 + 8) * 36 + nt * 4 + t] =
                    packh2(fmaxf(c[nt][2], 0.f), fmaxf(c[nt][3], 0.f));
            }
        }
        __syncwarp();

        // ---- L2 (fp16 k16): Ys -> C; relu; direct red.v2 scatter ----
        {
            float c[8][4];
#pragma unroll
            for (int nt = 0; nt < 8; nt++) {
                const float2 bb = *(const float2*)(bs2 + nt * 8 + 2 * t);
                c[nt][0] = bb.x; c[nt][1] = bb.y; c[nt][2] = bb.x; c[nt][3] = bb.y;
            }
#pragma unroll
            for (int kt = 0; kt < 4; kt++) {
                const int kb = kt * 8;
                const unsigned a0 = Ysu[(r0)     * 36 + kb + t];
                const unsigned a1 = Ysu[(r0 + 8) * 36 + kb + t];
                const unsigned a2 = Ysu[(r0)     * 36 + kb + t + 4];
                const unsigned a3 = Ysu[(r0 + 8) * 36 + kb + t + 4];
#pragma unroll
                for (int nt = 0; nt < 8; nt++) {
                    const unsigned b0r = W2u[(nt * 8 + g) * 36 + kb + t];
                    const unsigned b1r = W2u[(nt * 8 + g) * 36 + kb + t + 4];
                    mma16(c[nt], a0, a1, a2, a3, b0r, b1r);
                }
            }
            const int da = sdst[r0], db = sdst[r0 + 8];
#pragma unroll
            for (int nt = 0; nt < 8; nt++) {
                const int col = nt * 8 + 2 * t;
                const float v0 = fmaxf(c[nt][0], 0.f), v1 = fmaxf(c[nt][1], 0.f);
                const float v2 = fmaxf(c[nt][2], 0.f), v3 = fmaxf(c[nt][3], 0.f);
                asm volatile("red.global.add.v2.f32 [%0], {%1,%2};"
                             :: "l"(g_new + (size_t)da * 64 + col), "f"(v0), "f"(v1) : "memory");
                asm volatile("red.global.add.v2.f32 [%0], {%1,%2};"
                             :: "l"(g_new + (size_t)db * 64 + col), "f"(v2), "f"(v3) : "memory");
            }
        }
        __syncwarp();
    }
}

// ====================== readout kernel (persistent, tf32, as R12) ======================
template<int KDIM, int NT, int ASTRIDE, int WSTRIDE, int YSTRIDE, bool ROUND>
__device__ __forceinline__ void mlp_layer(
    const float* __restrict__ As, const float* __restrict__ Wt,
    const float* __restrict__ bias, float* __restrict__ Ys,
    int warp, int gg, int t)
{
    float c[NT][4];
#pragma unroll
    for (int nt = 0; nt < NT; nt++) {
        float v0 = bias[nt * 8 + 2 * t];
        float v1 = bias[nt * 8 + 2 * t + 1];
        c[nt][0] = v0; c[nt][1] = v1; c[nt][2] = v0; c[nt][3] = v1;
    }
    const unsigned* Au = (const unsigned*)As;
    const unsigned* Wu = (const unsigned*)Wt;
    const int row0 = warp * 16 + gg;
#pragma unroll
    for (int kt = 0; kt < KDIM / 8; kt++) {
        const int kb = kt * 8;
        unsigned a[4];
        a[0] = Au[(size_t)row0       * ASTRIDE + kb + t];
        a[1] = Au[(size_t)(row0 + 8) * ASTRIDE + kb + t];
        a[2] = Au[(size_t)row0       * ASTRIDE + kb + t + 4];
        a[3] = Au[(size_t)(row0 + 8) * ASTRIDE + kb + t + 4];
#pragma unroll
        for (int nt = 0; nt < NT; nt++) {
            unsigned b[2];
            b[0] = Wu[(nt * 8 + gg) * WSTRIDE + kb + t];
            b[1] = Wu[(nt * 8 + gg) * WSTRIDE + kb + t + 4];
            mma8(c[nt], a, b);
        }
    }
#pragma unroll
    for (int nt = 0; nt < NT; nt++) {
        const int col = nt * 8 + 2 * t;
        float v0 = fmaxf(c[nt][0], 0.f), v1 = fmaxf(c[nt][1], 0.f);
        float v2 = fmaxf(c[nt][2], 0.f), v3 = fmaxf(c[nt][3], 0.f);
        if (ROUND) { v0 = rna_f(v0); v1 = rna_f(v1); v2 = rna_f(v2); v3 = rna_f(v3); }
        Ys[(size_t)row0       * YSTRIDE + col]     = v0;
        Ys[(size_t)row0       * YSTRIDE + col + 1] = v1;
        Ys[(size_t)(row0 + 8) * YSTRIDE + col]     = v2;
        Ys[(size_t)(row0 + 8) * YSTRIDE + col + 1] = v3;
    }
}

#define R_XS    0
#define R_Y0    (R_XS + 128*68)
#define R_W1T   (R_Y0 + 128*68)
#define R_W2T   (R_W1T + 64*68)
#define R_W3T   (R_W2T + 64*68)
#define R_B1    (R_W3T + 16*68)
#define R_B2    (R_B1 + 64)
#define R_B3    (R_B2 + 64)
#define R_SMEM_FLOATS (R_B3 + 16)
#define R_SMEM_BYTES  (R_SMEM_FLOATS * 4)

__global__ void __launch_bounds__(256, 2) readout_kernel(
    const float* __restrict__ fc1w, const float* __restrict__ fc1b,
    const float* __restrict__ fc2w, const float* __restrict__ fc2b,
    const float* __restrict__ outw, const float* __restrict__ outb,
    float* __restrict__ out)
{
    extern __shared__ float sm[];
    float* Xs  = sm + R_XS;
    float* Y0  = sm + R_Y0;
    float* W1t = sm + R_W1T;
    float* W2t = sm + R_W2T;
    float* W3t = sm + R_W3T;
    float* bsa = sm + R_B1;
    float* bsb = sm + R_B2;
    float* bsc = sm + R_B3;

    const int tid  = threadIdx.x;
    const int warp = tid >> 5, lane = tid & 31;
    const int gg = lane >> 2, t = lane & 3;

    for (int i = tid; i < 64 * 64; i += 256) {
        int k = i >> 6, n = i & 63;
        W1t[n * 68 + k] = rna_f(fc1w[i]);
        W2t[n * 68 + k] = rna_f(fc2w[i]);
    }
    for (int i = tid; i < 64 * 16; i += 256) {
        int k = i >> 4, n = i & 15;
        W3t[n * 68 + k] = rna_f(outw[i]);
    }
    if (tid < 64) { bsa[tid] = fc1b[tid]; bsb[tid] = fc2b[tid]; }
    if (tid < 16) bsc[tid] = outb[tid];

    const float* g_new = (const float*)g_new_states4;

    for (int tile = blockIdx.x; tile < N_ATILES; tile += gridDim.x) {
        __syncthreads();
        for (int i = tid; i < 128 * 16; i += 256) {
            const int rr = i >> 4, q = i & 15;
            const float4 v = *(const float4*)(g_new + ((size_t)tile * 128 + rr) * 64 + q * 4);
            float4 o;
            o.x = rna_f(v.x); o.y = rna_f(v.y); o.z = rna_f(v.z); o.w = rna_f(v.w);
            *(float4*)(Xs + (size_t)rr * 68 + q * 4) = o;
        }
        __syncthreads();

        mlp_layer<64, 8, 68, 68, 68, true >(Xs, W1t, bsa, Y0, warp, gg, t);
        __syncthreads();
        mlp_layer<64, 8, 68, 68, 68, true >(Y0, W2t, bsb, Xs, warp, gg, t);
        __syncthreads();
        mlp_layer<64, 2, 68, 68, 16, false>(Xs, W3t, bsc, Y0, warp, gg, t);
        __syncthreads();

        if (tid < 64) {
            const int mol = tid >> 4, col = tid & 15;
            float s = 0.f;
#pragma unroll
            for (int rr = 0; rr < 32; rr++) s += Y0[(mol * 32 + rr) * 16 + col];
            out[((size_t)tile * 4 + mol) * 16 + col] = s;
        }
    }
}

extern "C" void kernel_launch(void* const* d_in, const int* in_sizes, int n_in,
                              void* d_out, int out_size) {
    const float* atom_states = (const float*)d_in[0];
    const int*   edge_src    = (const int*)d_in[1];
    const int*   edge_dst    = (const int*)d_in[2];
    const float* ms0w = (const float*)d_in[4];  const float* ms0b = (const float*)d_in[5];
    const float* ms1w = (const float*)d_in[6];  const float* ms1b = (const float*)d_in[7];
    const float* ms2w = (const float*)d_in[8];  const float* ms2b = (const float*)d_in[9];
    const float* fc1w = (const float*)d_in[10]; const float* fc1b = (const float*)d_in[11];
    const float* fc2w = (const float*)d_in[12]; const float* fc2b = (const float*)d_in[13];
    const float* outw = (const float*)d_in[14]; const float* outb = (const float*)d_in[15];
    float* out = (float*)d_out;

    cudaFuncSetAttribute(pq_kernel, cudaFuncAttributeMaxDynamicSharedMemorySize, PQ_SMEM_BYTES);
    cudaFuncSetAttribute(edge_kernel, cudaFuncAttributeMaxDynamicSharedMemorySize, EH_SMEM_BYTES);
    cudaFuncSetAttribute(readout_kernel, cudaFuncAttributeMaxDynamicSharedMemorySize, R_SMEM_BYTES);

    int sms = 148;
    cudaDeviceGetAttribute(&sms, cudaDevAttrMultiProcessorCount, 0);

    pq_kernel<<<2 * sms, 256, PQ_SMEM_BYTES>>>(atom_states, ms0w);
    edge_kernel<<<3 * sms, 256, EH_SMEM_BYTES>>>(edge_src, edge_dst,
                                                 ms0b, ms1w, ms1b, ms2w, ms2b);
    readout_kernel<<<2 * sms, 256, R_SMEM_BYTES>>>(fc1w, fc1b, fc2w, fc2b,
                                                   outw, outb, out);
}

// round 14
// speedup vs baseline: 1.5430x; 1.0525x over previous
#include <cuda_runtime.h>
#include <cuda_fp16.h>
#include <cstdint>

#define N_ATOMS   131072
#define N_EDGES   1048576
#define DSTATE    64
#define N_MOLS    4096
#define ETILE     128
#define N_ETILES  (N_EDGES / ETILE)   // 8192
#define N_ATILES  (N_ATOMS / 128)     // 1024

__device__ float4 g_new_states4[N_ATOMS * DSTATE / 4];
__device__ uint4  g_Ph4[N_ATOMS * 8];   // P as fp16: 64 halfs = 8 uint4 per atom
__device__ uint4  g_Qh4[N_ATOMS * 8];

__device__ __forceinline__ uint32_t smem_u32(const void* p) {
    uint32_t a;
    asm("{ .reg .u64 t; cvta.to.shared.u64 t, %1; cvt.u32.u64 %0, t; }" : "=r"(a) : "l"(p));
    return a;
}

// fp16 m16n8k16, fp32 accum
__device__ __forceinline__ void mma16(float* c, unsigned a0, unsigned a1,
                                      unsigned a2, unsigned a3,
                                      unsigned b0, unsigned b1) {
    asm volatile(
        "mma.sync.aligned.m16n8k16.row.col.f32.f16.f16.f32 "
        "{%0,%1,%2,%3}, {%4,%5,%6,%7}, {%8,%9}, {%0,%1,%2,%3};"
        : "+f"(c[0]), "+f"(c[1]), "+f"(c[2]), "+f"(c[3])
        : "r"(a0), "r"(a1), "r"(a2), "r"(a3), "r"(b0), "r"(b1));
}

__device__ __forceinline__ unsigned packh2(float lo, float hi) {
    __half2 h = __floats2half2_rn(lo, hi);
    return *(unsigned*)&h;
}

__device__ __forceinline__ void cp16(uint32_t dst, const void* src) {
    asm volatile("cp.async.cg.shared.global [%0], [%1], 16;" :: "r"(dst), "l"(src));
}
__device__ __forceinline__ void cp_commit() { asm volatile("cp.async.commit_group;" ::: "memory"); }
__device__ __forceinline__ void cp_wait0()  { asm volatile("cp.async.wait_group 0;" ::: "memory"); }
__device__ __forceinline__ void cp_wait1()  { asm volatile("cp.async.wait_group 1;" ::: "memory"); }

// ====================== P/Q precompute kernel (fp16 mma, fp16 output) ======================
#define PQ_XR0  0
#define PQ_XR1  8704
#define PQ_W    17408                 // uints region: 2 x 64*36
#define PQ_SMEM_FLOATS (PQ_W + 2*64*36)
#define PQ_SMEM_BYTES  (PQ_SMEM_FLOATS * 4)

__device__ __forceinline__ void pq_layer_h16(
    const float* __restrict__ Xr, const unsigned* __restrict__ Wu,
    unsigned* __restrict__ gOut, int warp, int g, int t)
{
    float c[8][4];
#pragma unroll
    for (int nt = 0; nt < 8; nt++)
        c[nt][0] = c[nt][1] = c[nt][2] = c[nt][3] = 0.f;
    const int row0 = warp * 16 + g;
#pragma unroll
    for (int kt = 0; kt < 4; kt++) {
        const int kb = kt * 8;
        const int k0 = 2 * (kb + t), k1 = 2 * (kb + t + 4);
        const float2 f0 = *(const float2*)(Xr + (row0)     * 68 + k0);
        const float2 f1 = *(const float2*)(Xr + (row0 + 8) * 68 + k0);
        const float2 f2 = *(const float2*)(Xr + (row0)     * 68 + k1);
        const float2 f3 = *(const float2*)(Xr + (row0 + 8) * 68 + k1);
        const unsigned a0 = packh2(f0.x, f0.y);
        const unsigned a1 = packh2(f1.x, f1.y);
        const unsigned a2 = packh2(f2.x, f2.y);
        const unsigned a3 = packh2(f3.x, f3.y);
#pragma unroll
        for (int nt = 0; nt < 8; nt++) {
            const unsigned b0 = Wu[(nt * 8 + g) * 36 + kb + t];
            const unsigned b1 = Wu[(nt * 8 + g) * 36 + kb + t + 4];
            mma16(c[nt], a0, a1, a2, a3, b0, b1);
        }
    }
#pragma unroll
    for (int nt = 0; nt < 8; nt++) {
        gOut[(size_t)(row0)     * 32 + nt * 4 + t] = packh2(c[nt][0], c[nt][1]);
        gOut[(size_t)(row0 + 8) * 32 + nt * 4 + t] = packh2(c[nt][2], c[nt][3]);
    }
}

__global__ void __launch_bounds__(256, 2) pq_kernel(
    const float* __restrict__ atom_states,
    const float* __restrict__ w0)
{
    extern __shared__ float sm[];
    unsigned* Wt = (unsigned*)(sm + PQ_W);
    unsigned* Wb = Wt + 64 * 36;
    const uint32_t base = smem_u32(sm);

    const int tid  = threadIdx.x;
    const int warp = tid >> 5, lane = tid & 31;
    const int g = lane >> 2, t = lane & 3;
    const int stride = gridDim.x;

    for (int i = tid; i < 64 * 64; i += 256) {
        int k = i >> 6, n = i & 63;
        ((__half*)Wt)[n * 72 + k] = __float2half_rn(w0[k * 64 + n]);
        ((__half*)Wb)[n * 72 + k] = __float2half_rn(w0[(k + 64) * 64 + n]);
    }

    if (blockIdx.x < N_ATILES) {
        const float* src = atom_states + (size_t)blockIdx.x * 128 * 64;
#pragma unroll
        for (int c = 0; c < 8; c++) {
            int id = c * 256 + tid;
            int row = id >> 4, off = id & 15;
            cp16(base + (uint32_t)(PQ_XR0 + row * 68 + off * 4) * 4u,
                 src + (size_t)row * 64 + off * 4);
        }
        cp_commit();
    }

    int it = 0;
    for (int tile = blockIdx.x; tile < N_ATILES; tile += stride, it++) {
        const int tn = tile + stride;
        if (tn < N_ATILES) {
            const float* src = atom_states + (size_t)tn * 128 * 64;
            const uint32_t dbuf = ((it + 1) & 1) ? PQ_XR1 : PQ_XR0;
#pragma unroll
            for (int c = 0; c < 8; c++) {
                int id = c * 256 + tid;
                int row = id >> 4, off = id & 15;
                cp16(base + (dbuf + (uint32_t)(row * 68 + off * 4)) * 4u,
                     src + (size_t)row * 64 + off * 4);
            }
            cp_commit();
            cp_wait1();
        } else {
            cp_wait0();
        }
        __syncthreads();

        const float* Xr = sm + ((it & 1) ? PQ_XR1 : PQ_XR0);
        unsigned* gP = (unsigned*)g_Ph4 + (size_t)tile * 128 * 32;
        unsigned* gQ = (unsigned*)g_Qh4 + (size_t)tile * 128 * 32;
        pq_layer_h16(Xr, Wt, gP, warp, g, t);
        pq_layer_h16(Xr, Wb, gQ, warp, g, t);

        float4* gz = g_new_states4 + (size_t)tile * 128 * 16;
        const float4 z = make_float4(0.f, 0.f, 0.f, 0.f);
        for (int i = tid; i < 128 * 16; i += 256) gz[i] = z;
        __syncthreads();
    }
}

// ====================== edge kernel (unchanged from R13) ======================
#define EH_A0   0
#define EH_YS   (128*36)
#define EH_W1   (EH_YS + 128*36)
#define EH_W2   (EH_W1 + 64*36)
#define EH_B0   (EH_W2 + 64*36)
#define EH_B1   (EH_B0 + 64)
#define EH_B2   (EH_B1 + 64)
#define EH_DST  (EH_B2 + 64)
#define EH_SRC  (EH_DST + 128)
#define EH_UINTS (EH_SRC + 128)
#define EH_SMEM_BYTES (EH_UINTS * 4)

__global__ void __launch_bounds__(256, 3) edge_kernel(
    const int* __restrict__ edge_src,
    const int* __restrict__ edge_dst,
    const float* __restrict__ b0,
    const float* __restrict__ w1, const float* __restrict__ b1,
    const float* __restrict__ w2, const float* __restrict__ b2)
{
    extern __shared__ unsigned smu[];
    unsigned* A0u = smu + EH_A0;
    unsigned* Ysu = smu + EH_YS;
    unsigned* W1u = smu + EH_W1;
    unsigned* W2u = smu + EH_W2;
    float* bs0 = (float*)(smu + EH_B0);
    float* bs1 = (float*)(smu + EH_B1);
    float* bs2 = (float*)(smu + EH_B2);
    int* sdst = (int*)(smu + EH_DST);
    int* ssrc = (int*)(smu + EH_SRC);

    const int tid  = threadIdx.x;
    const int warp = tid >> 5, lane = tid & 31;
    const int g = lane >> 2, t = lane & 3;
    const int wbase = warp * 16;

    for (int i = tid; i < 64 * 64; i += 256) {
        int k = i >> 6, n = i & 63;
        ((__half*)W1u)[n * 72 + k] = __float2half_rn(w1[i]);
        ((__half*)W2u)[n * 72 + k] = __float2half_rn(w2[i]);
    }
    if (tid < 64) { bs0[tid] = b0[tid]; bs1[tid] = b1[tid]; bs2[tid] = b2[tid]; }
    __syncthreads();

    const uint4* gP = g_Ph4;
    const uint4* gQ = g_Qh4;
    float* g_new = (float*)g_new_states4;

    for (int tile = blockIdx.x; tile < N_ETILES; tile += gridDim.x) {
        const int e0 = tile * ETILE + wbase;

        if (lane < 16)      sdst[wbase + lane]        = edge_dst[e0 + lane];
        else                ssrc[wbase + (lane - 16)] = edge_src[e0 + lane - 16];
        __syncwarp();

#pragma unroll
        for (int c = 0; c < 4; c++) {
            const int i = c * 32 + lane;
            const int rl = i >> 3, q = i & 7;
            const int r = wbase + rl;
            const uint4 pu = gP[(size_t)sdst[r] * 8 + q];
            const uint4 su = gQ[(size_t)ssrc[r] * 8 + q];
            const __half2* ph = (const __half2*)&pu;
            const __half2* sh = (const __half2*)&su;
            uint4 o;
            unsigned* ou = (unsigned*)&o;
#pragma unroll
            for (int j = 0; j < 4; j++) {
                const float2 pf = __half22float2(ph[j]);
                const float2 sf = __half22float2(sh[j]);
                const int col = q * 8 + 2 * j;
                ou[j] = packh2(fmaxf(pf.x + sf.x + bs0[col],     0.f),
                               fmaxf(pf.y + sf.y + bs0[col + 1], 0.f));
            }
            *(uint4*)(A0u + (size_t)r * 36 + q * 4) = o;
        }
        __syncwarp();

        const int r0 = wbase + g;

        {
            float c[8][4];
#pragma unroll
            for (int nt = 0; nt < 8; nt++) {
                const float2 bb = *(const float2*)(bs1 + nt * 8 + 2 * t);
                c[nt][0] = bb.x; c[nt][1] = bb.y; c[nt][2] = bb.x; c[nt][3] = bb.y;
            }
#pragma unroll
            for (int kt = 0; kt < 4; kt++) {
                const int kb = kt * 8;
                const unsigned a0 = A0u[(r0)     * 36 + kb + t];
                const unsigned a1 = A0u[(r0 + 8) * 36 + kb + t];
                const unsigned a2 = A0u[(r0)     * 36 + kb + t + 4];
                const unsigned a3 = A0u[(r0 + 8) * 36 + kb + t + 4];
#pragma unroll
                for (int nt = 0; nt < 8; nt++) {
                    const unsigned b0r = W1u[(nt * 8 + g) * 36 + kb + t];
                    const unsigned b1r = W1u[(nt * 8 + g) * 36 + kb + t + 4];
                    mma16(c[nt], a0, a1, a2, a3, b0r, b1r);
                }
            }
#pragma unroll
            for (int nt = 0; nt < 8; nt++) {
                Ysu[(r0)     * 36 + nt * 4 + t] =
                    packh2(fmaxf(c[nt][0], 0.f), fmaxf(c[nt][1], 0.f));
                Ysu[(r0 + 8) * 36 + nt * 4 + t] =
                    packh2(fmaxf(c[nt][2], 0.f), fmaxf(c[nt][3], 0.f));
            }
        }
        __syncwarp();

        {
            float c[8][4];
#pragma unroll
            for (int nt = 0; nt < 8; nt++) {
                const float2 bb = *(const float2*)(bs2 + nt * 8 + 2 * t);
                c[nt][0] = bb.x; c[nt][1] = bb.y; c[nt][2] = bb.x; c[nt][3] = bb.y;
            }
#pragma unroll
            for (int kt = 0; kt < 4; kt++) {
                const int kb = kt * 8;
                const unsigned a0 = Ysu[(r0)     * 36 + kb + t];
                const unsigned a1 = Ysu[(r0 + 8) * 36 + kb + t];
                const unsigned a2 = Ysu[(r0)     * 36 + kb + t + 4];
                const unsigned a3 = Ysu[(r0 + 8) * 36 + kb + t + 4];
#pragma unroll
                for (int nt = 0; nt < 8; nt++) {
                    const unsigned b0r = W2u[(nt * 8 + g) * 36 + kb + t];
                    const unsigned b1r = W2u[(nt * 8 + g) * 36 + kb + t + 4];
                    mma16(c[nt], a0, a1, a2, a3, b0r, b1r);
                }
            }
            const int da = sdst[r0], db = sdst[r0 + 8];
#pragma unroll
            for (int nt = 0; nt < 8; nt++) {
                const int col = nt * 8 + 2 * t;
                const float v0 = fmaxf(c[nt][0], 0.f), v1 = fmaxf(c[nt][1], 0.f);
                const float v2 = fmaxf(c[nt][2], 0.f), v3 = fmaxf(c[nt][3], 0.f);
                asm volatile("red.global.add.v2.f32 [%0], {%1,%2};"
                             :: "l"(g_new + (size_t)da * 64 + col), "f"(v0), "f"(v1) : "memory");
                asm volatile("red.global.add.v2.f32 [%0], {%1,%2};"
                             :: "l"(g_new + (size_t)db * 64 + col), "f"(v2), "f"(v3) : "memory");
            }
        }
        __syncwarp();
    }
}

// ====================== readout kernel: fp16 m16n8k16, 3 CTAs/SM ======================
// uints: Xs 128*36 (fp16), Ys 128*36 (fp16; O floats overlay during L3)
#define RH_XS   0
#define RH_YS   (128*36)
#define RH_W1   (RH_YS + 128*36)
#define RH_W2   (RH_W1 + 64*36)
#define RH_W3   (RH_W2 + 64*36)      // 16*36
#define RH_B1   (RH_W3 + 16*36)      // 64 floats
#define RH_B2   (RH_B1 + 64)
#define RH_B3   (RH_B2 + 64)         // 16 floats
#define RH_UINTS (RH_B3 + 16)
#define RH_SMEM_BYTES (RH_UINTS * 4)

__global__ void __launch_bounds__(256, 3) readout_kernel(
    const float* __restrict__ fc1w, const float* __restrict__ fc1b,
    const float* __restrict__ fc2w, const float* __restrict__ fc2b,
    const float* __restrict__ outw, const float* __restrict__ outb,
    float* __restrict__ out)
{
    extern __shared__ unsigned smu[];
    unsigned* Xsu = smu + RH_XS;
    unsigned* Ysu = smu + RH_YS;
    float*    Of  = (float*)(smu + RH_YS);   // overlays Ys during L3/output
    unsigned* W1u = smu + RH_W1;
    unsigned* W2u = smu + RH_W2;
    unsigned* W3u = smu + RH_W3;
    float* bs1 = (float*)(smu + RH_B1);
    float* bs2 = (float*)(smu + RH_B2);
    float* bs3 = (float*)(smu + RH_B3);

    const int tid  = threadIdx.x;
    const int warp = tid >> 5, lane = tid & 31;
    const int g = lane >> 2, t = lane & 3;

    for (int i = tid; i < 64 * 64; i += 256) {
        int k = i >> 6, n = i & 63;
        ((__half*)W1u)[n * 72 + k] = __float2half_rn(fc1w[i]);
        ((__half*)W2u)[n * 72 + k] = __float2half_rn(fc2w[i]);
    }
    for (int i = tid; i < 64 * 16; i += 256) {
        int k = i >> 4, n = i & 15;
        ((__half*)W3u)[n * 72 + k] = __float2half_rn(outw[i]);
    }
    if (tid < 64) { bs1[tid] = fc1b[tid]; bs2[tid] = fc2b[tid]; }
    if (tid < 16) bs3[tid] = outb[tid];

    const float* g_new = (const float*)g_new_states4;
    const int r0 = warp * 16 + g;

    for (int tile = blockIdx.x; tile < N_ATILES; tile += gridDim.x) {
        __syncthreads();   // prev tile's O consumed / weights ready on first iter
        // stage: g_new tile -> Xs fp16
        for (int i = tid; i < 128 * 16; i += 256) {
            const int rr = i >> 4, q = i & 15;
            const float4 v = *(const float4*)(g_new + ((size_t)tile * 128 + rr) * 64 + q * 4);
            uint2 u;
            u.x = packh2(v.x, v.y);
            u.y = packh2(v.z, v.w);
            *(uint2*)(Xsu + (size_t)rr * 36 + q * 2) = u;
        }
        __syncthreads();

        // L1: Xs -> Ys (fp16, relu)
        {
            float c[8][4];
#pragma unroll
            for (int nt = 0; nt < 8; nt++) {
                const float2 bb = *(const float2*)(bs1 + nt * 8 + 2 * t);
                c[nt][0] = bb.x; c[nt][1] = bb.y; c[nt][2] = bb.x; c[nt][3] = bb.y;
            }
#pragma unroll
            for (int kt = 0; kt < 4; kt++) {
                const int kb = kt * 8;
                const unsigned a0 = Xsu[(r0)     * 36 + kb + t];
                const unsigned a1 = Xsu[(r0 + 8) * 36 + kb + t];
                const unsigned a2 = Xsu[(r0)     * 36 + kb + t + 4];
                const unsigned a3 = Xsu[(r0 + 8) * 36 + kb + t + 4];
#pragma unroll
                for (int nt = 0; nt < 8; nt++) {
                    const unsigned b0r = W1u[(nt * 8 + g) * 36 + kb + t];
                    const unsigned b1r = W1u[(nt * 8 + g) * 36 + kb + t + 4];
                    mma16(c[nt], a0, a1, a2, a3, b0r, b1r);
                }
            }
#pragma unroll
            for (int nt = 0; nt < 8; nt++) {
                Ysu[(r0)     * 36 + nt * 4 + t] =
                    packh2(fmaxf(c[nt][0], 0.f), fmaxf(c[nt][1], 0.f));
                Ysu[(r0 + 8) * 36 + nt * 4 + t] =
                    packh2(fmaxf(c[nt][2], 0.f), fmaxf(c[nt][3], 0.f));
            }
        }
        __syncthreads();

        // L2: Ys -> Xs (fp16, relu)
        {
            float c[8][4];
#pragma unroll
            for (int nt = 0; nt < 8; nt++) {
                const float2 bb = *(const float2*)(bs2 + nt * 8 + 2 * t);
                c[nt][0] = bb.x; c[nt][1] = bb.y; c[nt][2] = bb.x; c[nt][3] = bb.y;
            }
#pragma unroll
            for (int kt = 0; kt < 4; kt++) {
                const int kb = kt * 8;
                const unsigned a0 = Ysu[(r0)     * 36 + kb + t];
                const unsigned a1 = Ysu[(r0 + 8) * 36 + kb + t];
                const unsigned a2 = Ysu[(r0)     * 36 + kb + t + 4];
                const unsigned a3 = Ysu[(r0 + 8) * 36 + kb + t + 4];
#pragma unroll
                for (int nt = 0; nt < 8; nt++) {
                    const unsigned b0r = W2u[(nt * 8 + g) * 36 + kb + t];
                    const unsigned b1r = W2u[(nt * 8 + g) * 36 + kb + t + 4];
                    mma16(c[nt], a0, a1, a2, a3, b0r, b1r);
                }
            }
#pragma unroll
            for (int nt = 0; nt < 8; nt++) {
                Xsu[(r0)     * 36 + nt * 4 + t] =
                    packh2(fmaxf(c[nt][0], 0.f), fmaxf(c[nt][1], 0.f));
                Xsu[(r0 + 8) * 36 + nt * 4 + t] =
                    packh2(fmaxf(c[nt][2], 0.f), fmaxf(c[nt][3], 0.f));
            }
        }
        __syncthreads();

        // L3: Xs -> O (floats, 16 cols, relu); O overlays Ys region
        {
            float c[2][4];
#pragma unroll
            for (int nt = 0; nt < 2; nt++) {
                const float2 bb = *(const float2*)(bs3 + nt * 8 + 2 * t);
                c[nt][0] = bb.x; c[nt][1] = bb.y; c[nt][2] = bb.x; c[nt][3] = bb.y;
            }
#pragma unroll
            for (int kt = 0; kt < 4; kt++) {
                const int kb = kt * 8;
                const unsigned a0 = Xsu[(r0)     * 36 + kb + t];
                const unsigned a1 = Xsu[(r0 + 8) * 36 + kb + t];
                const unsigned a2 = Xsu[(r0)     * 36 + kb + t + 4];
                const unsigned a3 = Xsu[(r0 + 8) * 36 + kb + t + 4];
#pragma unroll
                for (int nt = 0; nt < 2; nt++) {
                    const unsigned b0r = W3u[(nt * 8 + g) * 36 + kb + t];
                    const unsigned b1r = W3u[(nt * 8 + g) * 36 + kb + t + 4];
                    mma16(c[nt], a0, a1, a2, a3, b0r, b1r);
                }
            }
#pragma unroll
            for (int nt = 0; nt < 2; nt++) {
                const int col = nt * 8 + 2 * t;
                *(float2*)(Of + (r0)     * 16 + col) =
                    make_float2(fmaxf(c[nt][0], 0.f), fmaxf(c[nt][1], 0.f));
                *(float2*)(Of + (r0 + 8) * 16 + col) =
                    make_float2(fmaxf(c[nt][2], 0.f), fmaxf(c[nt][3], 0.f));
            }
        }
        __syncthreads();

        // molecule sums: 128-atom tile = 4 molecules of 32
        if (tid < 64) {
            const int mol = tid >> 4, col = tid & 15;
            float s = 0.f;
#pragma unroll
            for (int rr = 0; rr < 32; rr++) s += Of[(mol * 32 + rr) * 16 + col];
            out[((size_t)tile * 4 + mol) * 16 + col] = s;
        }
    }
}

extern "C" void kernel_launch(void* const* d_in, const int* in_sizes, int n_in,
                              void* d_out, int out_size) {
    const float* atom_states = (const float*)d_in[0];
    const int*   edge_src    = (const int*)d_in[1];
    const int*   edge_dst    = (const int*)d_in[2];
    const float* ms0w = (const float*)d_in[4];  const float* ms0b = (const float*)d_in[5];
    const float* ms1w = (const float*)d_in[6];  const float* ms1b = (const float*)d_in[7];
    const float* ms2w = (const float*)d_in[8];  const float* ms2b = (const float*)d_in[9];
    const float* fc1w = (const float*)d_in[10]; const float* fc1b = (const float*)d_in[11];
    const float* fc2w = (const float*)d_in[12]; const float* fc2b = (const float*)d_in[13];
    const float* outw = (const float*)d_in[14]; const float* outb = (const float*)d_in[15];
    float* out = (float*)d_out;

    cudaFuncSetAttribute(pq_kernel, cudaFuncAttributeMaxDynamicSharedMemorySize, PQ_SMEM_BYTES);
    cudaFuncSetAttribute(edge_kernel, cudaFuncAttributeMaxDynamicSharedMemorySize, EH_SMEM_BYTES);
    cudaFuncSetAttribute(readout_kernel, cudaFuncAttributeMaxDynamicSharedMemorySize, RH_SMEM_BYTES);

    int sms = 148;
    cudaDeviceGetAttribute(&sms, cudaDevAttrMultiProcessorCount, 0);

    pq_kernel<<<2 * sms, 256, PQ_SMEM_BYTES>>>(atom_states, ms0w);
    edge_kernel<<<3 * sms, 256, EH_SMEM_BYTES>>>(edge_src, edge_dst,
                                                 ms0b, ms1w, ms1b, ms2w, ms2b);
    readout_kernel<<<3 * sms, 256, RH_SMEM_BYTES>>>(fc1w, fc1b, fc2w, fc2b,
                                                    outw, outb, out);
}